// round 2
// baseline (speedup 1.0000x reference)
#include <cuda_runtime.h>

#define N_NODES 100000
#define F_IN    64
#define H_DIM   32
#define C_DIM   5
#define H2_STRIDE 8   // pad 5 -> 8 floats so rows are 16B aligned for v4 atomics

// Scratch (device globals: no allocation allowed)
__device__ float g_deg [N_NODES];
__device__ float g_dinv[N_NODES];
__device__ float g_h   [N_NODES * H_DIM];     // x @ W1
__device__ float g_agg1[N_NODES * H_DIM];     // layer-1 aggregation
__device__ float g_h2  [N_NODES * H2_STRIDE]; // x1 @ W2
__device__ float g_agg2[N_NODES * H2_STRIDE]; // layer-2 aggregation

__device__ __forceinline__ void red_add_v4(float* p, float a, float b, float c, float d) {
    asm volatile("red.global.add.v4.f32 [%0], {%1, %2, %3, %4};"
                 :: "l"(p), "f"(a), "f"(b), "f"(c), "f"(d) : "memory");
}
__device__ __forceinline__ void red_add_f32(float* p, float a) {
    asm volatile("red.global.add.f32 [%0], %1;" :: "l"(p), "f"(a) : "memory");
}

// ---------------- degree + normalization ----------------

__global__ void k_init_deg() {
    int i = blockIdx.x * blockDim.x + threadIdx.x;
    if (i < N_NODES) g_deg[i] = 1.0f;   // self-loop weight
}

__global__ void k_deg(const int* __restrict__ dst,
                      const float* __restrict__ w, int E) {
    int e = blockIdx.x * blockDim.x + threadIdx.x;
    if (e < E) red_add_f32(&g_deg[dst[e]], w[e]);
}

__global__ void k_dinv() {
    int i = blockIdx.x * blockDim.x + threadIdx.x;
    if (i < N_NODES) g_dinv[i] = rsqrtf(g_deg[i]);   // deg >= 1 always
}

// ---------------- layer 1: h = x@W1 ; agg1 = self-loop term ----------------

__global__ void k_gemm1(const float* __restrict__ x, const float* __restrict__ W1) {
    __shared__ float Ws[F_IN * H_DIM];
    for (int i = threadIdx.x; i < F_IN * H_DIM; i += blockDim.x) Ws[i] = W1[i];
    __syncthreads();

    int n = blockIdx.x * blockDim.x + threadIdx.x;
    if (n >= N_NODES) return;

    const float4* xr = (const float4*)(x + (size_t)n * F_IN);
    float acc[H_DIM];
#pragma unroll
    for (int j = 0; j < H_DIM; j++) acc[j] = 0.f;

#pragma unroll
    for (int k4 = 0; k4 < F_IN / 4; k4++) {
        float4 xv = xr[k4];
        const float* w0 = &Ws[(k4 * 4 + 0) * H_DIM];
        const float* w1 = &Ws[(k4 * 4 + 1) * H_DIM];
        const float* w2 = &Ws[(k4 * 4 + 2) * H_DIM];
        const float* w3 = &Ws[(k4 * 4 + 3) * H_DIM];
#pragma unroll
        for (int j = 0; j < H_DIM; j++)
            acc[j] += xv.x * w0[j] + xv.y * w1[j] + xv.z * w2[j] + xv.w * w3[j];
    }

    float s  = g_dinv[n];
    float s2 = s * s;
    float* hp = g_h    + (size_t)n * H_DIM;
    float* ap = g_agg1 + (size_t)n * H_DIM;
#pragma unroll
    for (int j = 0; j < H_DIM; j++) { hp[j] = acc[j]; ap[j] = acc[j] * s2; }
}

__global__ void k_scatter1(const int* __restrict__ src,
                           const int* __restrict__ dst,
                           const float* __restrict__ w, int E) {
    int e = blockIdx.x * blockDim.x + threadIdx.x;
    if (e >= E) return;
    int s = src[e], d = dst[e];
    float nrm = g_dinv[s] * w[e] * g_dinv[d];
    const float4* hs = (const float4*)(g_h + (size_t)s * H_DIM);
    float* ad = g_agg1 + (size_t)d * H_DIM;
#pragma unroll
    for (int i = 0; i < H_DIM / 4; i++) {
        float4 v = hs[i];
        red_add_v4(ad + i * 4, v.x * nrm, v.y * nrm, v.z * nrm, v.w * nrm);
    }
}

// x1 = relu(agg1 + b1), written to d_out region [N*C, N*C + N*H)
__global__ void k_relu_bias(const float* __restrict__ b1, float* __restrict__ x1out) {
    int i = blockIdx.x * blockDim.x + threadIdx.x;
    if (i >= N_NODES * H_DIM) return;
    int j = i & (H_DIM - 1);
    float v = g_agg1[i] + b1[j];
    x1out[i] = v > 0.f ? v : 0.f;
}

// ---------------- layer 2: h2 = x1@W2 ; agg2 = self-loop term ----------------

__global__ void k_gemm2(const float* __restrict__ x1, const float* __restrict__ W2) {
    __shared__ float Ws[H_DIM * C_DIM];
    for (int i = threadIdx.x; i < H_DIM * C_DIM; i += blockDim.x) Ws[i] = W2[i];
    __syncthreads();

    int n = blockIdx.x * blockDim.x + threadIdx.x;
    if (n >= N_NODES) return;

    const float4* xr = (const float4*)(x1 + (size_t)n * H_DIM);
    float acc[C_DIM];
#pragma unroll
    for (int j = 0; j < C_DIM; j++) acc[j] = 0.f;

#pragma unroll
    for (int k4 = 0; k4 < H_DIM / 4; k4++) {
        float4 xv = xr[k4];
#pragma unroll
        for (int j = 0; j < C_DIM; j++) {
            acc[j] += xv.x * Ws[(k4 * 4 + 0) * C_DIM + j];
            acc[j] += xv.y * Ws[(k4 * 4 + 1) * C_DIM + j];
            acc[j] += xv.z * Ws[(k4 * 4 + 2) * C_DIM + j];
            acc[j] += xv.w * Ws[(k4 * 4 + 3) * C_DIM + j];
        }
    }

    float s  = g_dinv[n];
    float s2 = s * s;
    float* hp = g_h2   + (size_t)n * H2_STRIDE;
    float* ap = g_agg2 + (size_t)n * H2_STRIDE;
#pragma unroll
    for (int j = 0; j < C_DIM; j++) { hp[j] = acc[j]; ap[j] = acc[j] * s2; }
#pragma unroll
    for (int j = C_DIM; j < H2_STRIDE; j++) { hp[j] = 0.f; ap[j] = 0.f; }
}

__global__ void k_scatter2(const int* __restrict__ src,
                           const int* __restrict__ dst,
                           const float* __restrict__ w, int E) {
    int e = blockIdx.x * blockDim.x + threadIdx.x;
    if (e >= E) return;
    int s = src[e], d = dst[e];
    float nrm = g_dinv[s] * w[e] * g_dinv[d];
    const float* hs = g_h2 + (size_t)s * H2_STRIDE;
    float4 v = *(const float4*)hs;
    float v4 = hs[4];
    float* ad = g_agg2 + (size_t)d * H2_STRIDE;
    red_add_v4(ad, v.x * nrm, v.y * nrm, v.z * nrm, v.w * nrm);
    red_add_f32(ad + 4, v4 * nrm);
}

// x2 = agg2 + b2 -> d_out[0 : N*C)
__global__ void k_out2(const float* __restrict__ b2, float* __restrict__ out) {
    int i = blockIdx.x * blockDim.x + threadIdx.x;
    if (i >= N_NODES * C_DIM) return;
    int n = i / C_DIM;
    int j = i - n * C_DIM;
    out[i] = g_agg2[(size_t)n * H2_STRIDE + j] + b2[j];
}

// ---------------- launch ----------------

extern "C" void kernel_launch(void* const* d_in, const int* in_sizes, int n_in,
                              void* d_out, int out_size) {
    const float* x   = (const float*)d_in[0];
    const int*   ei  = (const int*)d_in[1];     // JAX demotes int64 -> int32
    const float* ew  = (const float*)d_in[2];
    const float* W1  = (const float*)d_in[3];
    const float* b1  = (const float*)d_in[4];
    const float* W2  = (const float*)d_in[5];
    const float* b2  = (const float*)d_in[6];
    float* out = (float*)d_out;

    const int E = in_sizes[2];
    const int* src = ei;
    const int* dst = ei + E;

    float* x2_out = out;                           // [N, C]
    float* x1_out = out + (size_t)N_NODES * C_DIM; // [N, H]

    const int T = 256;
    const int gN  = (N_NODES + T - 1) / T;
    const int gE  = (E + T - 1) / T;
    const int gNH = (N_NODES * H_DIM + T - 1) / T;
    const int gNC = (N_NODES * C_DIM + T - 1) / T;

    k_init_deg <<<gN,  T>>>();
    k_deg      <<<gE,  T>>>(dst, ew, E);
    k_dinv     <<<gN,  T>>>();
    k_gemm1    <<<gN,  T>>>(x, W1);
    k_scatter1 <<<gE,  T>>>(src, dst, ew, E);
    k_relu_bias<<<gNH, T>>>(b1, x1_out);
    k_gemm2    <<<gN,  T>>>(x1_out, W2);
    k_scatter2 <<<gE,  T>>>(src, dst, ew, E);
    k_out2     <<<gNC, T>>>(b2, x2_out);
}

// round 3
// speedup vs baseline: 1.7311x; 1.7311x over previous
#include <cuda_runtime.h>

#define N_NODES 100000
#define F_IN    64
#define H_DIM   32
#define C_DIM   5
#define H2_STRIDE 8
#define MAX_E   3400000
#define NB      ((N_NODES + 1023) / 1024)   // 98 scan blocks

// ---- scratch (device globals; no allocation allowed) ----
__device__ float g_deg [N_NODES];
__device__ float g_dinv[N_NODES];
__device__ int   g_cnt [N_NODES];
__device__ int   g_off [N_NODES + 1];
__device__ int   g_cur [N_NODES];
__device__ int   g_bsum [NB];
__device__ int   g_bbase[NB];
__device__ int2  g_edge[MAX_E];                 // {src, nrm-as-bits} grouped by dst
__device__ float g_h   [N_NODES * H_DIM];       // x @ W1
__device__ float g_h2  [N_NODES * H2_STRIDE];   // x1 @ W2 (padded)

__device__ __forceinline__ void red_add_f32(float* p, float a) {
    asm volatile("red.global.add.f32 [%0], %1;" :: "l"(p), "f"(a) : "memory");
}

// ---------------- build: histogram + weighted degree ----------------

__global__ void k_init() {
    int i = blockIdx.x * blockDim.x + threadIdx.x;
    if (i < N_NODES) { g_cnt[i] = 0; g_deg[i] = 1.0f; }   // self-loop weight
}

__global__ void k_hist_deg(const int* __restrict__ dst,
                           const float* __restrict__ w, int E) {
    int e = blockIdx.x * blockDim.x + threadIdx.x;
    if (e < E) {
        int d = dst[e];
        atomicAdd(&g_cnt[d], 1);
        red_add_f32(&g_deg[d], w[e]);
    }
}

__global__ void k_dinv() {
    int i = blockIdx.x * blockDim.x + threadIdx.x;
    if (i < N_NODES) g_dinv[i] = rsqrtf(g_deg[i]);   // deg >= 1 (self loop)
}

// ---------------- build: 2-level exclusive scan ----------------

__global__ void k_bsum() {
    __shared__ int wsum[8];
    int b = blockIdx.x, t = threadIdx.x;
    int base = b * 1024 + t * 4;
    int s = 0;
    if (base + 3 < N_NODES) {
        int4 v = *(const int4*)&g_cnt[base];
        s = v.x + v.y + v.z + v.w;
    } else {
        for (int j = 0; j < 4; j++) if (base + j < N_NODES) s += g_cnt[base + j];
    }
    for (int o = 16; o > 0; o >>= 1) s += __shfl_xor_sync(0xffffffffu, s, o);
    int lane = t & 31, wid = t >> 5;
    if (lane == 0) wsum[wid] = s;
    __syncthreads();
    if (t == 0) {
        int tot = 0;
        for (int i = 0; i < 8; i++) tot += wsum[i];
        g_bsum[b] = tot;
    }
}

__global__ void k_bscan() {   // 1 block, 32 threads: scan NB block sums
    int lane = threadIdx.x;
    int i = lane * 4;
    int v0 = (i     < NB) ? g_bsum[i]     : 0;
    int v1 = (i + 1 < NB) ? g_bsum[i + 1] : 0;
    int v2 = (i + 2 < NB) ? g_bsum[i + 2] : 0;
    int v3 = (i + 3 < NB) ? g_bsum[i + 3] : 0;
    int s = v0 + v1 + v2 + v3;
    int inc = s;
    for (int o = 1; o < 32; o <<= 1) {
        int u = __shfl_up_sync(0xffffffffu, inc, o);
        if (lane >= o) inc += u;
    }
    int excl = inc - s;
    if (i     < NB) g_bbase[i]     = excl;
    if (i + 1 < NB) g_bbase[i + 1] = excl + v0;
    if (i + 2 < NB) g_bbase[i + 2] = excl + v0 + v1;
    if (i + 3 < NB) g_bbase[i + 3] = excl + v0 + v1 + v2;
}

__global__ void k_offsets(int E) {
    __shared__ int wsum[8];
    int b = blockIdx.x, t = threadIdx.x;
    int base = b * 1024 + t * 4;
    int c0 = 0, c1 = 0, c2 = 0, c3 = 0;
    if (base + 3 < N_NODES) {
        int4 v = *(const int4*)&g_cnt[base];
        c0 = v.x; c1 = v.y; c2 = v.z; c3 = v.w;
    } else {
        if (base     < N_NODES) c0 = g_cnt[base];
        if (base + 1 < N_NODES) c1 = g_cnt[base + 1];
        if (base + 2 < N_NODES) c2 = g_cnt[base + 2];
        if (base + 3 < N_NODES) c3 = g_cnt[base + 3];
    }
    int s = c0 + c1 + c2 + c3;
    int lane = t & 31, wid = t >> 5;
    int inc = s;
    for (int o = 1; o < 32; o <<= 1) {
        int u = __shfl_up_sync(0xffffffffu, inc, o);
        if (lane >= o) inc += u;
    }
    if (lane == 31) wsum[wid] = inc;
    __syncthreads();
    if (wid == 0) {
        int v = (lane < 8) ? wsum[lane] : 0;
        for (int o = 1; o < 8; o <<= 1) {
            int u = __shfl_up_sync(0xffffffffu, v, o);
            if (lane >= o) v += u;
        }
        if (lane < 8) wsum[lane] = v;   // inclusive warp sums
    }
    __syncthreads();
    int blockexcl = (wid == 0) ? 0 : wsum[wid - 1];
    int excl = g_bbase[b] + blockexcl + (inc - s);
    if (base     < N_NODES) { g_off[base]     = excl;            g_cur[base]     = excl; }
    if (base + 1 < N_NODES) { int o1 = excl + c0;       g_off[base + 1] = o1; g_cur[base + 1] = o1; }
    if (base + 2 < N_NODES) { int o2 = excl + c0 + c1;  g_off[base + 2] = o2; g_cur[base + 2] = o2; }
    if (base + 3 < N_NODES) { int o3 = excl + c0 + c1 + c2; g_off[base + 3] = o3; g_cur[base + 3] = o3; }
    if (b == 0 && t == 0) g_off[N_NODES] = E;
}

__global__ void k_fill(const int* __restrict__ src, const int* __restrict__ dst,
                       const float* __restrict__ w, int E) {
    int e = blockIdx.x * blockDim.x + threadIdx.x;
    if (e >= E) return;
    int s = src[e], d = dst[e];
    float nrm = g_dinv[s] * w[e] * g_dinv[d];
    int p = atomicAdd(&g_cur[d], 1);
    g_edge[p] = make_int2(s, __float_as_int(nrm));
}

// ---------------- layer 1 ----------------

// h = x @ W1 : 2 threads/node, 16 outputs each, W1 in shared as float4
__global__ void k_gemm1(const float* __restrict__ x, const float* __restrict__ W1) {
    __shared__ float4 Ws[F_IN * H_DIM / 4];   // 512 float4 = [k][j4], j4 in 0..7
    for (int i = threadIdx.x; i < F_IN * H_DIM / 4; i += blockDim.x)
        Ws[i] = ((const float4*)W1)[i];
    __syncthreads();

    int t = blockIdx.x * blockDim.x + threadIdx.x;
    int node = t >> 1;
    if (node >= N_NODES) return;
    int half = t & 1;
    int jb = half * 4;   // float4 column offset

    const float4* xr = (const float4*)(x + (size_t)node * F_IN);
    float acc[16];
#pragma unroll
    for (int j = 0; j < 16; j++) acc[j] = 0.f;

#pragma unroll
    for (int k4 = 0; k4 < F_IN / 4; k4++) {
        float4 xv = xr[k4];
#pragma unroll
        for (int r = 0; r < 4; r++) {
            int k = k4 * 4 + r;
            float xs = (r == 0) ? xv.x : (r == 1) ? xv.y : (r == 2) ? xv.z : xv.w;
#pragma unroll
            for (int j4 = 0; j4 < 4; j4++) {
                float4 wv = Ws[k * 8 + jb + j4];
                acc[j4 * 4 + 0] += xs * wv.x;
                acc[j4 * 4 + 1] += xs * wv.y;
                acc[j4 * 4 + 2] += xs * wv.z;
                acc[j4 * 4 + 3] += xs * wv.w;
            }
        }
    }
    float4* hp = (float4*)(g_h + (size_t)node * H_DIM + half * 16);
#pragma unroll
    for (int j4 = 0; j4 < 4; j4++)
        hp[j4] = make_float4(acc[j4 * 4 + 0], acc[j4 * 4 + 1], acc[j4 * 4 + 2], acc[j4 * 4 + 3]);
}

// agg1 pull: warp per node, lane = feature. Fuses +b1 and ReLU -> x1_out.
__global__ void k_agg1(const float* __restrict__ b1, float* __restrict__ x1out) {
    int node = (blockIdx.x * blockDim.x + threadIdx.x) >> 5;
    if (node >= N_NODES) return;
    int lane = threadIdx.x & 31;
    int beg = g_off[node], end = g_off[node + 1];
    float dv = g_dinv[node];
    float acc = g_h[(size_t)node * H_DIM + lane] * dv * dv;   // self loop

    for (int e = beg; e < end; e += 32) {
        int idx = e + lane;
        int   sE = 0;
        float nrE = 0.f;
        if (idx < end) {
            int2 ed = g_edge[idx];
            sE = ed.x; nrE = __int_as_float(ed.y);
        }
        int n = end - e; if (n > 32) n = 32;
        for (int i = 0; i < n; i += 8) {
            int   s0[8];
            float nr0[8], v0[8];
#pragma unroll
            for (int j = 0; j < 8; j++) {
                s0[j]  = __shfl_sync(0xffffffffu, sE, i + j);
                nr0[j] = __shfl_sync(0xffffffffu, nrE, i + j);
            }
#pragma unroll
            for (int j = 0; j < 8; j++)
                v0[j] = g_h[(size_t)s0[j] * H_DIM + lane];
#pragma unroll
            for (int j = 0; j < 8; j++)
                acc += nr0[j] * v0[j];
        }
    }
    float v = acc + b1[lane];
    x1out[(size_t)node * H_DIM + lane] = v > 0.f ? v : 0.f;
}

// ---------------- layer 2 ----------------

__global__ void k_gemm2(const float* __restrict__ x1, const float* __restrict__ W2) {
    __shared__ float Ws[H_DIM * C_DIM];
    for (int i = threadIdx.x; i < H_DIM * C_DIM; i += blockDim.x) Ws[i] = W2[i];
    __syncthreads();

    int n = blockIdx.x * blockDim.x + threadIdx.x;
    if (n >= N_NODES) return;

    const float4* xr = (const float4*)(x1 + (size_t)n * H_DIM);
    float acc[C_DIM];
#pragma unroll
    for (int j = 0; j < C_DIM; j++) acc[j] = 0.f;

#pragma unroll
    for (int k4 = 0; k4 < H_DIM / 4; k4++) {
        float4 xv = xr[k4];
#pragma unroll
        for (int j = 0; j < C_DIM; j++) {
            acc[j] += xv.x * Ws[(k4 * 4 + 0) * C_DIM + j];
            acc[j] += xv.y * Ws[(k4 * 4 + 1) * C_DIM + j];
            acc[j] += xv.z * Ws[(k4 * 4 + 2) * C_DIM + j];
            acc[j] += xv.w * Ws[(k4 * 4 + 3) * C_DIM + j];
        }
    }
    float4* hp = (float4*)(g_h2 + (size_t)n * H2_STRIDE);
    hp[0] = make_float4(acc[0], acc[1], acc[2], acc[3]);
    hp[1] = make_float4(acc[4], 0.f, 0.f, 0.f);
}

// agg2 pull: warp per node, 4 edges x 8 features per step. Fuses +b2 -> out.
__global__ void k_agg2(const float* __restrict__ b2, float* __restrict__ out) {
    int node = (blockIdx.x * blockDim.x + threadIdx.x) >> 5;
    if (node >= N_NODES) return;
    int lane = threadIdx.x & 31;
    int f = lane & 7, stripe = lane >> 3;   // 4 stripes of 8 features
    int beg = g_off[node], end = g_off[node + 1];
    float dv = g_dinv[node];
    float acc = (stripe == 0) ? g_h2[(size_t)node * H2_STRIDE + f] * dv * dv : 0.f;

    int e = beg + stripe;
    for (; e + 4 < end; e += 8) {   // 2-deep pipeline
        int2 a = g_edge[e];
        int2 b = g_edge[e + 4];
        float va = g_h2[(size_t)a.x * H2_STRIDE + f];
        float vb = g_h2[(size_t)b.x * H2_STRIDE + f];
        acc += __int_as_float(a.y) * va;
        acc += __int_as_float(b.y) * vb;
    }
    if (e < end) {
        int2 a = g_edge[e];
        acc += __int_as_float(a.y) * g_h2[(size_t)a.x * H2_STRIDE + f];
    }
    acc += __shfl_xor_sync(0xffffffffu, acc, 8);
    acc += __shfl_xor_sync(0xffffffffu, acc, 16);
    if (lane < C_DIM) out[(size_t)node * C_DIM + lane] = acc + b2[lane];
}

// ---------------- launch ----------------

extern "C" void kernel_launch(void* const* d_in, const int* in_sizes, int n_in,
                              void* d_out, int out_size) {
    const float* x   = (const float*)d_in[0];
    const int*   ei  = (const int*)d_in[1];     // JAX demotes int64 -> int32
    const float* ew  = (const float*)d_in[2];
    const float* W1  = (const float*)d_in[3];
    const float* b1  = (const float*)d_in[4];
    const float* W2  = (const float*)d_in[5];
    const float* b2  = (const float*)d_in[6];
    float* out = (float*)d_out;

    const int E = in_sizes[2];
    const int* src = ei;
    const int* dst = ei + E;

    float* x2_out = out;                            // [N, C]
    float* x1_out = out + (size_t)N_NODES * C_DIM;  // [N, H]

    const int T = 256;
    const int gN   = (N_NODES + T - 1) / T;
    const int gE   = (E + T - 1) / T;
    const int gN2  = (N_NODES * 2 + T - 1) / T;          // gemm1: 2 threads/node
    const int gW   = (N_NODES * 32 + T - 1) / T;         // warp/node kernels

    k_init    <<<gN,  T>>>();
    k_hist_deg<<<gE,  T>>>(dst, ew, E);
    k_dinv    <<<gN,  T>>>();
    k_bsum    <<<NB,  T>>>();
    k_bscan   <<<1,  32>>>();
    k_offsets <<<NB,  T>>>(E);
    k_fill    <<<gE,  T>>>(src, dst, ew, E);
    k_gemm1   <<<gN2, T>>>(x, W1);
    k_agg1    <<<gW,  T>>>(b1, x1_out);
    k_gemm2   <<<gN,  T>>>(x1_out, W2);
    k_agg2    <<<gW,  T>>>(b2, x2_out);
}